// round 16
// baseline (speedup 1.0000x reference)
#include <cuda_runtime.h>
#include <cuda_fp16.h>
#include <cstdint>
#include <cstddef>

#define BATCH 1024
#define INF   512
#define OUTF  100000
#define NTILE 1042           // 1042*96 = 100032 >= 100000

#define MARGIN_COS 0.8775825618903728f
#define MARGIN_SIN 0.4794255386042030f
#define LOGIT_SCALE 20.0f
#define W_PRESCALE 64.0f

static __device__ __half d_fhat[BATCH * INF];   // normalized features fp16

// ---------------------------------------------------------------------------
// helpers
// ---------------------------------------------------------------------------
#define LDSM4(fr, saddr) \
    asm volatile("ldmatrix.sync.aligned.m8n8.x4.shared.b16 {%0,%1,%2,%3},[%4];" \
                 : "=r"((fr)[0]), "=r"((fr)[1]), "=r"((fr)[2]), "=r"((fr)[3]) : "r"(saddr))

__device__ __forceinline__ void mma16816(float* c, const uint32_t* a, uint32_t b0, uint32_t b1) {
    asm volatile(
        "mma.sync.aligned.m16n8k16.row.col.f32.f16.f16.f32 "
        "{%0,%1,%2,%3},{%4,%5,%6,%7},{%8,%9},{%0,%1,%2,%3};"
        : "+f"(c[0]), "+f"(c[1]), "+f"(c[2]), "+f"(c[3])
        : "r"(a[0]), "r"(a[1]), "r"(a[2]), "r"(a[3]), "r"(b0), "r"(b1));
}
__device__ __forceinline__ void cp_async16(uint32_t dst, const void* src) {
    asm volatile("cp.async.cg.shared.global [%0], [%1], 16;" :: "r"(dst), "l"(src));
}
#define CP_COMMIT() asm volatile("cp.async.commit_group;" ::: "memory")
#define CP_WAIT(N)  asm volatile("cp.async.wait_group %0;" :: "n"(N) : "memory")

// ---------------------------------------------------------------------------
// Kernel 1: normalize features rows (exact fp32 norm), write fp16
// ---------------------------------------------------------------------------
__global__ void norm_features_k(const float* __restrict__ f) {
    int b = blockIdx.x;
    int t = threadIdx.x;  // 128 threads
    const float4* f4 = reinterpret_cast<const float4*>(f + (size_t)b * INF);
    float4 v = f4[t];
    float ss = v.x * v.x + v.y * v.y + v.z * v.z + v.w * v.w;
#pragma unroll
    for (int o = 16; o; o >>= 1) ss += __shfl_xor_sync(0xFFFFFFFFu, ss, o);
    __shared__ float red[4];
    if ((t & 31) == 0) red[t >> 5] = ss;
    __syncthreads();
    ss = red[0] + red[1] + red[2] + red[3];
    float inv = 1.0f / fmaxf(sqrtf(ss), 1e-12f);
    __half2* o2 = reinterpret_cast<__half2*>(d_fhat + (size_t)b * INF + t * 4);
    o2[0] = __floats2half2_rn(v.x * inv, v.y * inv);
    o2[1] = __floats2half2_rn(v.z * inv, v.w * inv);
}

// ---------------------------------------------------------------------------
// Kernel 3: margin fixup — rewrite the 1024 (row, target) cells exactly.
// ---------------------------------------------------------------------------
__global__ void margin_fixup_k(const int* __restrict__ targets, float* __restrict__ out) {
    int r = blockIdx.x * 128 + threadIdx.x;
    if (r >= BATCH) return;
    int t = targets[r];
    float v = out[(size_t)r * OUTF + t] * (1.0f / LOGIT_SCALE);
    float y = v * MARGIN_COS - sqrtf(fmaxf(1.0f - v * v, 0.0f)) * MARGIN_SIN;
    out[(size_t)r * OUTF + t] = y * LOGIT_SCALE;
}

// ---------------------------------------------------------------------------
// Fused GEMM: 256 threads = 8 warps (4M x 2N), warp tile 64x48, per 96-class
//  N-tile. W fp32 read once -> fp16 SMEM resident (shared, read-only).
//  A: PER-WARP PRIVATE 3-stage ring (4 KB/stage, ldsm-native contiguous
//  layout) filled by per-warp cp.async -> NO __syncthreads in the main loop.
//  Epilogue margin-free (fixup kernel applies the 1024 target margins).
// ---------------------------------------------------------------------------
#define LDSW 520                      // halves per W row (1040B: conflict-free ldsm)
#define SMEM_WINV 0
#define SMEM_W    1024
#define SMEM_A    (1024 + 96 * LDSW * 2)           // 100864
#define AWARP_SZ  (3 * 4096)                       // 3 stages x 4 KB
#define SMEM_TOTAL (SMEM_A + 8 * AWARP_SZ)         // 199168

__global__ void __launch_bounds__(256, 1)
arcface_fused_k(const float* __restrict__ w, float* __restrict__ out) {
    extern __shared__ char smem[];
    const uint32_t sb = (uint32_t)__cvta_generic_to_shared(smem);
    const int tid  = threadIdx.x;
    const int lane = tid & 31;
    const int wid  = tid >> 5;
    const int wm   = wid & 3;   // 4 warps in M (64 rows each)
    const int wn   = wid >> 2;  // 2 warps in N (48 cols each)
    const int nblk = blockIdx.x * 96;

    float* winv_s = reinterpret_cast<float*>(smem + SMEM_WINV);
    const uint32_t w_base  = sb + SMEM_W;
    const uint32_t aw_base = sb + SMEM_A + (uint32_t)wid * AWARP_SZ;

    // lane-constant decomposition for cp.async fill
    const int lr  = lane >> 2;          // row offset within 8-row group
    const int lks = (lane >> 1) & 1;    // k16 select
    const int lhi = lane & 1;           // 8-half column select
    const int arow0 = wm * 64;          // this warp's first A row (within slab)

    // ---- prologue: prefetch chunks 0,1,2 (slab 0) into stages 0,1,2 ----
#pragma unroll
    for (int pq = 0; pq < 3; ++pq) {
        const uint32_t wstage = aw_base + (uint32_t)pq * 4096;
#pragma unroll
        for (int j = 0; j < 8; ++j) {
            const int row = j * 8 + lr;
            const uint32_t dst = wstage +
                (uint32_t)((((row >> 4) * 2 + lks) * 512) + lhi * 256 + (row & 15) * 16);
            const char* src = (const char*)(d_fhat + ((size_t)(arow0 + row) << 9))
                              + pq * 64 + lks * 32 + lhi * 16;
            cp_async16(dst, src);
        }
        CP_COMMIT();
    }

    // ---- Phase 1: W fp32 -> fp16 SMEM (read once); winv premultiplied by 20 ----
    if (tid < 192) {
        const int r = tid >> 1;        // class row in tile (0..95)
        const int h = tid & 1;         // half-row (256 floats)
        const int cls = nblk + r;
        __half* wrow = reinterpret_cast<__half*>(smem + SMEM_W) + r * LDSW + h * 256;
        float ss = 0.0f;
        if (cls < OUTF) {
            const float4* src = reinterpret_cast<const float4*>(w + (size_t)cls * INF + h * 256);
#pragma unroll 8
            for (int j = 0; j < 64; ++j) {
                float4 v = src[j];
                ss += v.x * v.x + v.y * v.y + v.z * v.z + v.w * v.w;
                __half2* dst = reinterpret_cast<__half2*>(wrow + j * 4);
                dst[0] = __floats2half2_rn(v.x * W_PRESCALE, v.y * W_PRESCALE);
                dst[1] = __floats2half2_rn(v.z * W_PRESCALE, v.w * W_PRESCALE);
            }
        } else {
            __half2 z = __floats2half2_rn(0.f, 0.f);
#pragma unroll 8
            for (int j = 0; j < 64; ++j) {
                __half2* dst = reinterpret_cast<__half2*>(wrow + j * 4);
                dst[0] = z; dst[1] = z;
            }
        }
        float tot = ss + __shfl_xor_sync(0xFFFFFFFFu, ss, 1);
        if (h == 0)
            winv_s[r] = (cls < OUTF)
                ? LOGIT_SCALE / (W_PRESCALE * fmaxf(sqrtf(tot), 1e-12f)) : 0.0f;
    }
    __syncthreads();   // the ONLY block-wide sync (W visible to all warps)

    // ---- per-warp B ldsm base (padded-row layout, proven mapping) ----
    const uint32_t lane_col = ((lane >> 4) << 4);
    const uint32_t b_off0 = (uint32_t)((wn * 48 + (lane & 7) + (((lane >> 3) & 1) << 3)) * (LDSW * 2))
                            + lane_col;
    const uint32_t a_lane16 = (uint32_t)(lane * 16);

    uint32_t af[2][4][4];   // [ks][mi][reg]
    uint32_t bf[2][3][4];   // [ks][pi][reg]
    float acc[4][6][4];

    int stage = 0;          // q % 3, tracked incrementally

    for (int slab = 0; slab < 4; ++slab) {
#pragma unroll
        for (int i = 0; i < 4; i++)
#pragma unroll
            for (int j = 0; j < 6; j++)
#pragma unroll
                for (int q2 = 0; q2 < 4; q2++) acc[i][j][q2] = 0.0f;

#pragma unroll 1
        for (int kc = 0; kc < 16; ++kc) {
            const int q = slab * 16 + kc;
            CP_WAIT(2);             // chunk q's group complete (per-warp)
            __syncwarp();           // cross-lane smem visibility within warp

            const uint32_t st = aw_base + (uint32_t)stage * 4096;
            const uint32_t bo = (uint32_t)(kc * 64);

            // fragments for ks0 and ks1 (A: contiguous 512B blocks, conflict-free)
#pragma unroll
            for (int mi = 0; mi < 4; ++mi)
                LDSM4(af[0][mi], st + (uint32_t)(mi * 1024) + a_lane16);
#pragma unroll
            for (int i = 0; i < 3; ++i)
                LDSM4(bf[0][i], w_base + b_off0 + (uint32_t)(i * 16 * LDSW * 2) + bo);
#pragma unroll
            for (int mi = 0; mi < 4; ++mi)
                LDSM4(af[1][mi], st + (uint32_t)(mi * 1024 + 512) + a_lane16);
#pragma unroll
            for (int i = 0; i < 3; ++i)
                LDSM4(bf[1][i], w_base + b_off0 + (uint32_t)(i * 16 * LDSW * 2) + bo + 32);

            // 48-mma burst (2 x 24)
#pragma unroll
            for (int ks = 0; ks < 2; ++ks)
#pragma unroll
                for (int mi = 0; mi < 4; ++mi)
#pragma unroll
                    for (int ni = 0; ni < 6; ++ni) {
                        const int pi = ni >> 1, sub = ni & 1;
                        mma16816(acc[mi][ni], af[ks][mi], bf[ks][pi][sub], bf[ks][pi][sub + 2]);
                    }

            // prefetch chunk q+3 into the stage just freed (per-warp, no barrier)
            if (q + 3 < 64) {
                const int qn = q + 3;
                const int slabn = qn >> 4, kcn = qn & 15;
                const int rowg0 = slabn * 256 + arow0;
#pragma unroll
                for (int j = 0; j < 8; ++j) {
                    const int row = j * 8 + lr;
                    const uint32_t dst = st +
                        (uint32_t)((((row >> 4) * 2 + lks) * 512) + lhi * 256 + (row & 15) * 16);
                    const char* src = (const char*)(d_fhat + ((size_t)(rowg0 + row) << 9))
                                      + kcn * 64 + lks * 32 + lhi * 16;
                    cp_async16(dst, src);
                }
            }
            CP_COMMIT();            // exactly one group per iteration (may be empty)
            stage = (stage == 2) ? 0 : stage + 1;
        }

        // ---- margin-free epilogue for this slab (no sync; acc is private) ----
        const int rbase = slab * 256 + wm * 64 + (lane >> 2);
#pragma unroll
        for (int ni = 0; ni < 6; ++ni) {
            const int cl = wn * 48 + ni * 8 + (lane & 3) * 2;  // local col
            const int c0 = nblk + cl;
            if (c0 >= OUTF) continue;
            const float2 wv = *reinterpret_cast<const float2*>(winv_s + cl);
#pragma unroll
            for (int mi = 0; mi < 4; ++mi) {
#pragma unroll
                for (int rr = 0; rr < 2; ++rr) {
                    const int row = rbase + mi * 16 + rr * 8;
                    float x0 = fminf(fmaxf(acc[mi][ni][rr * 2 + 0] * wv.x, -LOGIT_SCALE), LOGIT_SCALE);
                    float x1 = fminf(fmaxf(acc[mi][ni][rr * 2 + 1] * wv.y, -LOGIT_SCALE), LOGIT_SCALE);
                    *reinterpret_cast<float2*>(out + (size_t)row * OUTF + c0) =
                        make_float2(x0, x1);
                }
            }
        }
    }
}

// ---------------------------------------------------------------------------
extern "C" void kernel_launch(void* const* d_in, const int* in_sizes, int n_in,
                              void* d_out, int out_size) {
    const float* feat = (const float*)d_in[0];
    const int*   tgt  = (const int*)d_in[1];   // int32 (JAX x64-disabled)
    const float* w    = (const float*)d_in[2];
    float* out = (float*)d_out;

    cudaFuncSetAttribute(arcface_fused_k, cudaFuncAttributeMaxDynamicSharedMemorySize, SMEM_TOTAL);
    norm_features_k<<<BATCH, 128>>>(feat);
    arcface_fused_k<<<NTILE, 256, SMEM_TOTAL>>>(w, out);
    margin_fixup_k<<<(BATCH + 127) / 128, 128>>>(tgt, out);
}

// round 17
// speedup vs baseline: 1.5949x; 1.5949x over previous
#include <cuda_runtime.h>
#include <cuda_fp16.h>
#include <cstdint>
#include <cstddef>

#define BATCH 1024
#define INF   512
#define OUTF  100000
#define NTILE 782            // 782*128 = 100096 >= 100000

#define MARGIN_COS 0.8775825618903728f
#define MARGIN_SIN 0.4794255386042030f
#define LOGIT_SCALE 20.0f
#define W_PRESCALE 64.0f

static __device__ __half d_fhat[BATCH * INF];   // normalized features fp16

// ---------------------------------------------------------------------------
// helpers
// ---------------------------------------------------------------------------
#define LDSM4(fr, saddr) \
    asm volatile("ldmatrix.sync.aligned.m8n8.x4.shared.b16 {%0,%1,%2,%3},[%4];" \
                 : "=r"((fr)[0]), "=r"((fr)[1]), "=r"((fr)[2]), "=r"((fr)[3]) : "r"(saddr))

__device__ __forceinline__ void mma16816(float* c, const uint32_t* a, uint32_t b0, uint32_t b1) {
    asm volatile(
        "mma.sync.aligned.m16n8k16.row.col.f32.f16.f16.f32 "
        "{%0,%1,%2,%3},{%4,%5,%6,%7},{%8,%9},{%0,%1,%2,%3};"
        : "+f"(c[0]), "+f"(c[1]), "+f"(c[2]), "+f"(c[3])
        : "r"(a[0]), "r"(a[1]), "r"(a[2]), "r"(a[3]), "r"(b0), "r"(b1));
}
__device__ __forceinline__ void cp_async16(uint32_t dst, const void* src) {
    asm volatile("cp.async.cg.shared.global [%0], [%1], 16;" :: "r"(dst), "l"(src));
}
#define CP_COMMIT() asm volatile("cp.async.commit_group;" ::: "memory")
#define CP_WAIT(N)  asm volatile("cp.async.wait_group %0;" :: "n"(N) : "memory")

// ---------------------------------------------------------------------------
// Kernel 1: normalize features rows (exact fp32 norm), write fp16
// ---------------------------------------------------------------------------
__global__ void norm_features_k(const float* __restrict__ f) {
    int b = blockIdx.x;
    int t = threadIdx.x;  // 128 threads
    const float4* f4 = reinterpret_cast<const float4*>(f + (size_t)b * INF);
    float4 v = f4[t];
    float ss = v.x * v.x + v.y * v.y + v.z * v.z + v.w * v.w;
#pragma unroll
    for (int o = 16; o; o >>= 1) ss += __shfl_xor_sync(0xFFFFFFFFu, ss, o);
    __shared__ float red[4];
    if ((t & 31) == 0) red[t >> 5] = ss;
    __syncthreads();
    ss = red[0] + red[1] + red[2] + red[3];
    float inv = 1.0f / fmaxf(sqrtf(ss), 1e-12f);
    __half2* o2 = reinterpret_cast<__half2*>(d_fhat + (size_t)b * INF + t * 4);
    o2[0] = __floats2half2_rn(v.x * inv, v.y * inv);
    o2[1] = __floats2half2_rn(v.z * inv, v.w * inv);
}

// ---------------------------------------------------------------------------
// Kernel 3: margin fixup — rewrite the 1024 (row, target) cells exactly.
// ---------------------------------------------------------------------------
__global__ void margin_fixup_k(const int* __restrict__ targets, float* __restrict__ out) {
    int r = blockIdx.x * 128 + threadIdx.x;
    if (r >= BATCH) return;
    int t = targets[r];
    float v = out[(size_t)r * OUTF + t] * (1.0f / LOGIT_SCALE);
    float y = v * MARGIN_COS - sqrtf(fmaxf(1.0f - v * v, 0.0f)) * MARGIN_SIN;
    out[(size_t)r * OUTF + t] = y * LOGIT_SCALE;
}

// ---------------------------------------------------------------------------
// Fused GEMM: 512 threads, 16 warps = 4M(64 rows) x 4N(32 cols) per 128-class
//  tile. Block tile 256(M) x 128(N); 4 M-passes. Per SM-ks: 96 ldsm (384cyc)
//  vs 256 HMMA (~560cyc) -> tensor-dominant ratio WITH 16-warp latency hiding.
//  W fp32 read once -> fp16 SMEM resident. A: 256x64-half chunks, double-
//  buffered cp.async (champion R15 wait/sync ordering). Margin-free epilogue.
// ---------------------------------------------------------------------------
#define LDSW 520                      // halves per W row (1040B: conflict-free ldsm)
#define LDSA 72                       // halves per A chunk row (144B: conflict-free)
#define SMEM_WINV 0
#define SMEM_W    1024
#define SMEM_A    (1024 + 128 * LDSW * 2)          // 134144
#define ABUF_SZ   (256 * LDSA * 2)                 // 36864
#define SMEM_TOTAL (SMEM_A + 2 * ABUF_SZ)          // 207872

__global__ void __launch_bounds__(512, 1)
arcface_fused_k(const float* __restrict__ w, float* __restrict__ out) {
    extern __shared__ char smem[];
    const uint32_t sb = (uint32_t)__cvta_generic_to_shared(smem);
    const int tid  = threadIdx.x;
    const int lane = tid & 31;
    const int wid  = tid >> 5;
    const int wm   = wid & 3;   // 4 warps in M (64 rows each)
    const int wn   = wid >> 2;  // 4 warps in N (32 cols each)
    const int nblk = blockIdx.x * 128;

    float* winv_s = reinterpret_cast<float*>(smem + SMEM_WINV);
    const uint32_t a_base = sb + SMEM_A;
    const uint32_t w_base = sb + SMEM_W;

    // ---- prefetch A chunk 0 (overlaps W phase): 256 rows x 64 halves ----
    {
#pragma unroll
        for (int k = 0; k < 4; ++k) {
            int i = tid + k * 512;           // 0..2047
            int r = i >> 3, g = i & 7;
            const char* src = (const char*)(d_fhat + ((size_t)r << 9)) + g * 16;
            cp_async16(a_base + r * (LDSA * 2) + g * 16, src);
        }
        CP_COMMIT();
    }

    // ---- Phase 1: W fp32 -> fp16 SMEM (read once); winv premultiplied by 20 ----
    {
        const int r = tid >> 2;        // class row in tile
        const int h = tid & 3;         // quarter-row (128 floats)
        const int cls = nblk + r;
        __half* wrow = reinterpret_cast<__half*>(smem + SMEM_W) + r * LDSW + h * 128;
        float ss = 0.0f;
        if (cls < OUTF) {
            const float4* src = reinterpret_cast<const float4*>(w + (size_t)cls * INF + h * 128);
#pragma unroll 8
            for (int j = 0; j < 32; ++j) {
                float4 v = src[j];
                ss += v.x * v.x + v.y * v.y + v.z * v.z + v.w * v.w;
                __half2* dst = reinterpret_cast<__half2*>(wrow + j * 4);
                dst[0] = __floats2half2_rn(v.x * W_PRESCALE, v.y * W_PRESCALE);
                dst[1] = __floats2half2_rn(v.z * W_PRESCALE, v.w * W_PRESCALE);
            }
        } else {
            __half2 z = __floats2half2_rn(0.f, 0.f);
#pragma unroll 8
            for (int j = 0; j < 32; ++j) {
                __half2* dst = reinterpret_cast<__half2*>(wrow + j * 4);
                dst[0] = z; dst[1] = z;
            }
        }
        float tot = ss + __shfl_xor_sync(0xFFFFFFFFu, ss, 1);
        tot += __shfl_xor_sync(0xFFFFFFFFu, tot, 2);
        if (h == 0)
            winv_s[r] = (cls < OUTF)
                ? LOGIT_SCALE / (W_PRESCALE * fmaxf(sqrtf(tot), 1e-12f)) : 0.0f;
    }
    CP_WAIT(0);
    __syncthreads();

    // ---- per-warp ldsm base addresses ----
    const uint32_t lane_col = ((lane >> 4) << 4);           // 0 or 16 bytes
    const uint32_t a_off0 = (uint32_t)((wm * 64 + (lane & 15)) * (LDSA * 2)) + lane_col;
    uint32_t b_addr[2];
    {
        const int br = wn * 32 + (lane & 7) + (((lane >> 3) & 1) << 3);
        b_addr[0] = w_base + (uint32_t)(br * (LDSW * 2)) + lane_col;
        b_addr[1] = b_addr[0] + 16 * (LDSW * 2);
    }

    uint32_t af[2][4][4];   // [buf][mi][reg]  (A: 4 x 16-row fragments)
    uint32_t bf[2][2][4];   // [buf][pi][reg]

    // preload fragments for chunk 0, ks 0
#pragma unroll
    for (int i = 0; i < 4; ++i)
        LDSM4(af[0][i], a_base + a_off0 + (uint32_t)(i * 16 * LDSA * 2));
    LDSM4(bf[0][0], b_addr[0]);
    LDSM4(bf[0][1], b_addr[1]);

    float acc[4][4][4];

    for (int m = 0; m < 4; ++m) {
#pragma unroll
        for (int i = 0; i < 4; i++)
#pragma unroll
            for (int j = 0; j < 4; j++)
#pragma unroll
                for (int q = 0; q < 4; q++) acc[i][j][q] = 0.0f;

#pragma unroll 1
        for (int kc = 0; kc < 8; ++kc) {
            const int q = m * 8 + kc;
            // prefetch next chunk into the other A buffer
            if (q + 1 < 32) {
                const int mn = (q + 1) >> 3, kn = (q + 1) & 7;
                const uint32_t dbuf = a_base + ((q + 1) & 1) * ABUF_SZ;
#pragma unroll
                for (int k = 0; k < 4; ++k) {
                    int i = tid + k * 512;
                    int r = i >> 3, g = i & 7;
                    const char* src = (const char*)(d_fhat + ((size_t)(mn * 256 + r) << 9))
                                      + kn * 128 + g * 16;
                    cp_async16(dbuf + r * (LDSA * 2) + g * 16, src);
                }
                CP_COMMIT();
                CP_WAIT(1);
            } else {
                CP_WAIT(0);
            }

            const uint32_t abuf = a_base + (q & 1) * ABUF_SZ;
            const uint32_t boff = (uint32_t)(kc * 128);
#pragma unroll
            for (int ks = 0; ks < 4; ++ks) {
                const int c = ks & 1, n = c ^ 1;
                if (ks < 3) {
                    const uint32_t ko = (uint32_t)((ks + 1) * 32);
#pragma unroll
                    for (int i = 0; i < 4; ++i)
                        LDSM4(af[n][i], abuf + a_off0 + (uint32_t)(i * 16 * LDSA * 2) + ko);
                    LDSM4(bf[n][0], b_addr[0] + boff + ko);
                    LDSM4(bf[n][1], b_addr[1] + boff + ko);
                }
                // 16-mma burst
#pragma unroll
                for (int mi = 0; mi < 4; ++mi)
#pragma unroll
                    for (int ni = 0; ni < 4; ++ni) {
                        const int pi = ni >> 1, sub = ni & 1;
                        mma16816(acc[mi][ni], af[c][mi], bf[c][pi][sub], bf[c][pi][sub + 2]);
                    }
            }
            CP_WAIT(0);
            __syncthreads();

            // preload ks0 fragments for the next chunk
            if (q + 1 < 32) {
                const uint32_t nabuf = a_base + ((q + 1) & 1) * ABUF_SZ;
                const uint32_t nboff = (uint32_t)(((kc + 1) & 7) * 128);
#pragma unroll
                for (int i = 0; i < 4; ++i)
                    LDSM4(af[0][i], nabuf + a_off0 + (uint32_t)(i * 16 * LDSA * 2));
                LDSM4(bf[0][0], b_addr[0] + nboff);
                LDSM4(bf[0][1], b_addr[1] + nboff);
            }
        }

        // ---- margin-free epilogue: clamp(acc*wv20) and store ----
        const int rbase = m * 256 + wm * 64 + (lane >> 2);
#pragma unroll
        for (int ni = 0; ni < 4; ++ni) {
            const int cl = wn * 32 + ni * 8 + (lane & 3) * 2;  // local col
            const int c0 = nblk + cl;
            if (c0 >= OUTF) continue;
            const float2 wv = *reinterpret_cast<const float2*>(winv_s + cl);
#pragma unroll
            for (int mi = 0; mi < 4; ++mi) {
#pragma unroll
                for (int rr = 0; rr < 2; ++rr) {
                    const int row = rbase + mi * 16 + rr * 8;
                    float x0 = fminf(fmaxf(acc[mi][ni][rr * 2 + 0] * wv.x, -LOGIT_SCALE), LOGIT_SCALE);
                    float x1 = fminf(fmaxf(acc[mi][ni][rr * 2 + 1] * wv.y, -LOGIT_SCALE), LOGIT_SCALE);
                    *reinterpret_cast<float2*>(out + (size_t)row * OUTF + c0) =
                        make_float2(x0, x1);
                }
            }
        }
    }
}

// ---------------------------------------------------------------------------
extern "C" void kernel_launch(void* const* d_in, const int* in_sizes, int n_in,
                              void* d_out, int out_size) {
    const float* feat = (const float*)d_in[0];
    const int*   tgt  = (const int*)d_in[1];   // int32 (JAX x64-disabled)
    const float* w    = (const float*)d_in[2];
    float* out = (float*)d_out;

    cudaFuncSetAttribute(arcface_fused_k, cudaFuncAttributeMaxDynamicSharedMemorySize, SMEM_TOTAL);
    norm_features_k<<<BATCH, 128>>>(feat);
    arcface_fused_k<<<NTILE, 512, SMEM_TOTAL>>>(w, out);
    margin_fixup_k<<<(BATCH + 127) / 128, 128>>>(tgt, out);
}